// round 4
// baseline (speedup 1.0000x reference)
#include <cuda_runtime.h>
#include <cstdint>

// ---------------- problem dims ----------------
#define B_DIM   4096
#define N_DIM   180
#define NV2     4096
#define IN_DIM  542
#define K1PAD   544            // IN_DIM padded to mult of 16
#define N2PAD   384            // 180 mu + 180 fb + 1 pi, padded to mult of 128

// output layout (flattened concat of reference tuple)
#define OUT_MU  0
#define OUT_PI  (B_DIM * N_DIM)                    //   737280
#define OUT_FB  (OUT_PI + B_DIM)                   //   741376
#define OUT_V   (OUT_FB + B_DIM * N_DIM)           //  1478656
#define OUT_Z   (OUT_V + (size_t)B_DIM * NV2)      // 18255872
#define OUT_X   (OUT_Z + (size_t)B_DIM * NV2)      // 35033088
#define OUT_B   (OUT_X + (size_t)B_DIM * NV2)      // 51810304

// constants (match python float64 -> f32 rounding)
#define BETA_MEM   0.951229424500714f      /* exp(-1/20)  */
#define RHO_ADAPT  0.9950124791926823f     /* exp(-1/200) */
#define ONE_M_RHO  0.004987520807317688f   /* 1 - exp(-1/200) */
#define BETA_ADAPT 1.8f
#define ALPHA_F    0.9f
#define PI_MAX     10.0f

// ---------------- device scratch (no allocs allowed) ----------------
__device__ float g_v2[(size_t)B_DIM * K1PAD];       // packed v2_input  [B,544]
__device__ float g_w2[(size_t)N2PAD * NV2];         // packed stage-2 W [384,4096]
__device__ float g_b2[N2PAD];                        // packed stage-2 bias
__device__ float g_logits[(size_t)B_DIM * N2PAD];   // stage-2 logits   [B,384]

// ---------------- pack kernels ----------------
__global__ void pack_v2_kernel(const float* __restrict__ xl4,
                               const float* __restrict__ xl23,
                               const float* __restrict__ cue,
                               const float* __restrict__ ts) {
    int i = blockIdx.x * blockDim.x + threadIdx.x;
    if (i >= B_DIM * K1PAD) return;
    int b = i / K1PAD, k = i % K1PAD;
    float v;
    if      (k < 180) v = xl4 [b * 180 + k];
    else if (k < 360) v = xl23[b * 180 + (k - 180)];
    else if (k < 540) v = cue [b * 180 + (k - 360)];
    else if (k < 542) v = ts  [b * 2   + (k - 540)];
    else              v = 0.0f;
    g_v2[i] = v;
}

__global__ void pack_w2_kernel(const float* __restrict__ Wmu, const float* __restrict__ bmu,
                               const float* __restrict__ Wfb, const float* __restrict__ bfb,
                               const float* __restrict__ Wpi, const float* __restrict__ bpi) {
    int i = blockIdx.x * blockDim.x + threadIdx.x;
    if (i < N2PAD) {
        float bv = 0.0f;
        if      (i < 180)  bv = bmu[i];
        else if (i < 360)  bv = bfb[i - 180];
        else if (i == 360) bv = bpi[0];
        g_b2[i] = bv;
    }
    if (i >= N2PAD * NV2) return;
    int r = i / NV2, k = i % NV2;
    float w = 0.0f;
    if      (r < 180)  w = Wmu[r * NV2 + k];
    else if (r < 360)  w = Wfb[(r - 180) * NV2 + k];
    else if (r == 360) w = Wpi[k];
    g_w2[i] = w;
}

// ---------------- GEMM micro-kernel (128x128x16 tile, 8x8/thread, f32x2 FFMA) --------
// Accumulates 16 k-steps into the given accumulator set (fresh per 64-k block in
// gemm1 for two-level blocked summation).
__device__ __forceinline__ void mma_tile16(unsigned long long acc[8][4],
                                           const float (*As)[130],
                                           const float (*Bs)[130],
                                           int tx, int ty) {
#pragma unroll
    for (int k = 0; k < 16; k++) {
        unsigned long long b2[4];
#pragma unroll
        for (int j = 0; j < 4; j++)
            b2[j] = *(const unsigned long long*)(&Bs[k][j * 32 + tx * 2]);
        unsigned long long a2[8];
#pragma unroll
        for (int i = 0; i < 8; i++) {
            unsigned u = __float_as_uint(As[k][ty * 8 + i]);
            asm("mov.b64 %0, {%1, %1};" : "=l"(a2[i]) : "r"(u));
        }
#pragma unroll
        for (int i = 0; i < 8; i++)
#pragma unroll
            for (int j = 0; j < 4; j++)
                asm("fma.rn.f32x2 %0, %1, %2, %0;"
                    : "+l"(acc[i][j]) : "l"(a2[i]), "l"(b2[j]));
    }
}

__device__ __forceinline__ void zero_acc(unsigned long long a[8][4]) {
#pragma unroll
    for (int i = 0; i < 8; i++)
#pragma unroll
        for (int j = 0; j < 4; j++) a[i][j] = 0ull;
}

// master += block  (packed f32x2 add, round-to-nearest per lane)
__device__ __forceinline__ void fold_acc(unsigned long long acc[8][4],
                                         unsigned long long blk[8][4]) {
#pragma unroll
    for (int i = 0; i < 8; i++)
#pragma unroll
        for (int j = 0; j < 4; j++)
            asm("add.rn.f32x2 %0, %0, %1;" : "+l"(acc[i][j]) : "l"(blk[i][j]));
}

// ---------------- kernel 1: drive GEMM + fused elementwise state update ----------
// Two-level blocked accumulation (b=64): each 64-k block is a fresh fma chain,
// folded into a short master chain. Error variance ~K*b/2 + K^2/(2b) instead of
// K^2/2  =>  ~5.8x smaller accumulation noise vs a single chain, minimizing
// divergence from the (multi-accumulator) reference backend.
// drive = (Sum_A + b_in) + Sum_B with Sum_A stashed to out[OUT_V] between phases.
__global__ __launch_bounds__(256, 1)
void gemm1_kernel(const float* __restrict__ xprev,
                  const float* __restrict__ Win,
                  const float* __restrict__ Wrec,
                  const float* __restrict__ bin,
                  const float* __restrict__ vprev,
                  const float* __restrict__ zprev,
                  const float* __restrict__ bprev,
                  const float* __restrict__ amask,
                  float* __restrict__ out) {
    __shared__ __align__(16) float As[16][130];
    __shared__ __align__(16) float Bs[16][130];

    const int tid = threadIdx.x;
    const int tx = tid & 15, ty = tid >> 4;
    const int bm = blockIdx.y * 128;     // batch rows
    const int bn = blockIdx.x * 128;     // neuron cols

    unsigned long long acc[8][4];        // master sum
    unsigned long long blk[8][4];        // fresh 64-k block sum
    zero_acc(acc);

    // ---- phase A: K over packed v2 input (542 real, 544 padded), W_in (ld=542) ----
    for (int kb = 0; kb < K1PAD; kb += 64) {
        zero_acc(blk);
        const int ntile = (K1PAD - kb >= 64) ? 4 : (K1PAD - kb) / 16;
        for (int t = 0; t < ntile; t++) {
            const int kk = kb + t * 16;
            __syncthreads();
#pragma unroll
            for (int q = 0; q < 2; q++) {                  // A tile: 512 float4
                int l = tid + q * 256;
                int r = l >> 2, c = (l & 3) * 4;
                float4 f = *(const float4*)(&g_v2[(size_t)(bm + r) * K1PAD + kk + c]);
                As[c + 0][r] = f.x; As[c + 1][r] = f.y; As[c + 2][r] = f.z; As[c + 3][r] = f.w;
            }
#pragma unroll
            for (int q = 0; q < 4; q++) {                  // W_in tile: float2, guarded tail
                int l = tid + q * 256;
                int r = l >> 3, c = (l & 7) * 2;
                int k = kk + c;
                float w0 = 0.0f, w1 = 0.0f;
                if (k + 1 < IN_DIM) {
                    float2 f = *(const float2*)(&Win[(size_t)(bn + r) * IN_DIM + k]);
                    w0 = f.x; w1 = f.y;
                } else if (k < IN_DIM) {
                    w0 = Win[(size_t)(bn + r) * IN_DIM + k];
                }
                Bs[c][r] = w0; Bs[c + 1][r] = w1;
            }
            __syncthreads();
            mma_tile16(blk, As, Bs, tx, ty);
        }
        fold_acc(acc, blk);
    }

    // ---- stash Sum_A (raw, no bias yet) into out[OUT_V] region; reset master ----
#pragma unroll
    for (int i = 0; i < 8; i++) {
        int gr = bm + ty * 8 + i;
#pragma unroll
        for (int j = 0; j < 4; j++) {
            int gc = bn + j * 32 + tx * 2;
            size_t idx = (size_t)gr * NV2 + gc;
            *(unsigned long long*)(&out[OUT_V + idx]) = acc[i][j];
        }
    }
    zero_acc(acc);

    // ---- phase B: blocked sum over x_prev (4096), W_rec ----
    for (int kb = 0; kb < NV2; kb += 64) {
        zero_acc(blk);
#pragma unroll 1
        for (int t = 0; t < 4; t++) {
            const int kk = kb + t * 16;
            __syncthreads();
#pragma unroll
            for (int q = 0; q < 2; q++) {
                int l = tid + q * 256;
                int r = l >> 2, c = (l & 3) * 4;
                float4 f = *(const float4*)(&xprev[(size_t)(bm + r) * NV2 + kk + c]);
                As[c + 0][r] = f.x; As[c + 1][r] = f.y; As[c + 2][r] = f.z; As[c + 3][r] = f.w;
                float4 g = *(const float4*)(&Wrec[(size_t)(bn + r) * NV2 + kk + c]);
                Bs[c + 0][r] = g.x; Bs[c + 1][r] = g.y; Bs[c + 2][r] = g.z; Bs[c + 3][r] = g.w;
            }
            __syncthreads();
            mma_tile16(blk, As, Bs, tx, ty);
        }
        fold_acc(acc, blk);
    }

    // ---- fused elementwise epilogue (explicit rn ops, reference order) ----
#pragma unroll
    for (int i = 0; i < 8; i++) {
        int gr = bm + ty * 8 + i;
#pragma unroll
        for (int j = 0; j < 4; j++) {
            int gc = bn + j * 32 + tx * 2;
            unsigned lo, hi;
            asm("mov.b64 {%0, %1}, %2;" : "=r"(lo), "=r"(hi) : "l"(acc[i][j]));
            size_t idx = (size_t)gr * NV2 + gc;
            float2 sA = *(const float2*)(&out[OUT_V + idx]);   // stashed Sum_A
            float2 bi = *(const float2*)(&bin[gc]);
            float2 am = *(const float2*)(&amask[gc]);
            float2 vp = *(const float2*)(&vprev[idx]);
            float2 zp = *(const float2*)(&zprev[idx]);
            float2 bp = *(const float2*)(&bprev[idx]);
            float2 xp = *(const float2*)(&xprev[idx]);

            // drive = (Sum_A + b_in) + Sum_B
            float d0 = __fadd_rn(__fadd_rn(sA.x, bi.x), __uint_as_float(lo));
            float d1 = __fadd_rn(__fadd_rn(sA.y, bi.y), __uint_as_float(hi));

            // v = ((beta * v_prev) + drive) - z_prev   (V_THRESH = 1.0 exact)
            float v0 = __fsub_rn(__fadd_rn(__fmul_rn(BETA_MEM, vp.x), d0), zp.x);
            float v1 = __fsub_rn(__fadd_rn(__fmul_rn(BETA_MEM, vp.y), d1), zp.y);
            // B_thresh = 1 + beta_adapt * b_prev ; z = (v - B_thresh) > 0
            float u0 = __fsub_rn(v0, __fadd_rn(1.0f, __fmul_rn(BETA_ADAPT, bp.x)));
            float u1 = __fsub_rn(v1, __fadd_rn(1.0f, __fmul_rn(BETA_ADAPT, bp.y)));
            float z0 = u0 > 0.0f ? 1.0f : 0.0f;
            float z1 = u1 > 0.0f ? 1.0f : 0.0f;
            // b = (rho*b_prev + (1-rho)*z) * mask
            float b0 = __fmul_rn(__fadd_rn(__fmul_rn(RHO_ADAPT, bp.x),
                                           __fmul_rn(ONE_M_RHO, z0)), am.x);
            float b1 = __fmul_rn(__fadd_rn(__fmul_rn(RHO_ADAPT, bp.y),
                                           __fmul_rn(ONE_M_RHO, z1)), am.y);
            // x = alpha*x_prev + z
            float x0 = __fadd_rn(__fmul_rn(ALPHA_F, xp.x), z0);
            float x1 = __fadd_rn(__fmul_rn(ALPHA_F, xp.y), z1);

            *(float2*)(&out[OUT_V + idx]) = make_float2(v0, v1);
            *(float2*)(&out[OUT_Z + idx]) = make_float2(z0, z1);
            *(float2*)(&out[OUT_X + idx]) = make_float2(x0, x1);
            *(float2*)(&out[OUT_B + idx]) = make_float2(b0, b1);
        }
    }
}

// ---------------- kernel 2: stage-2 GEMM  logits = x @ W2.T + b2 ----------------
__global__ __launch_bounds__(256, 2)
void gemm2_kernel(const float* __restrict__ out_base) {
    const float* x = out_base + OUT_X;   // new x written by gemm1
    __shared__ __align__(16) float As[16][130];
    __shared__ __align__(16) float Bs[16][130];

    const int tid = threadIdx.x;
    const int tx = tid & 15, ty = tid >> 4;
    const int bm = blockIdx.y * 128;     // batch rows
    const int bn = blockIdx.x * 128;     // output cols (0..383)

    unsigned long long acc[8][4];
    zero_acc(acc);

    for (int kk = 0; kk < NV2; kk += 16) {
        __syncthreads();
#pragma unroll
        for (int q = 0; q < 2; q++) {
            int l = tid + q * 256;
            int r = l >> 2, c = (l & 3) * 4;
            float4 f = *(const float4*)(&x[(size_t)(bm + r) * NV2 + kk + c]);
            As[c + 0][r] = f.x; As[c + 1][r] = f.y; As[c + 2][r] = f.z; As[c + 3][r] = f.w;
            float4 g = *(const float4*)(&g_w2[(size_t)(bn + r) * NV2 + kk + c]);
            Bs[c + 0][r] = g.x; Bs[c + 1][r] = g.y; Bs[c + 2][r] = g.z; Bs[c + 3][r] = g.w;
        }
        __syncthreads();
        mma_tile16(acc, As, Bs, tx, ty);
    }

#pragma unroll
    for (int i = 0; i < 8; i++) {
        int gr = bm + ty * 8 + i;
#pragma unroll
        for (int j = 0; j < 4; j++) {
            int gc = bn + j * 32 + tx * 2;
            unsigned lo, hi;
            asm("mov.b64 {%0, %1}, %2;" : "=r"(lo), "=r"(hi) : "l"(acc[i][j]));
            float2 r2;
            r2.x = __fadd_rn(__uint_as_float(lo), g_b2[gc]);
            r2.y = __fadd_rn(__uint_as_float(hi), g_b2[gc + 1]);
            *(float2*)(&g_logits[(size_t)gr * N2PAD + gc]) = r2;
        }
    }
}

// ---------------- kernel 3: softmax / feedback / softplus ----------------
__global__ void finish_kernel(float* __restrict__ out) {
    int b = blockIdx.x;
    int tid = threadIdx.x;                    // 256 threads
    const float* lg = &g_logits[(size_t)b * N2PAD];
    __shared__ float red[256];

    float l = (tid < N_DIM) ? lg[tid] : -3.0e38f;
    red[tid] = l;
    __syncthreads();
#pragma unroll
    for (int s = 128; s > 0; s >>= 1) {
        if (tid < s) red[tid] = fmaxf(red[tid], red[tid + s]);
        __syncthreads();
    }
    float m = red[0];
    __syncthreads();

    float e = (tid < N_DIM) ? expf(l - m) : 0.0f;
    red[tid] = e;
    __syncthreads();
#pragma unroll
    for (int s = 128; s > 0; s >>= 1) {
        if (tid < s) red[tid] += red[tid + s];
        __syncthreads();
    }
    float ssum = red[0];

    if (tid < N_DIM) {
        out[OUT_MU + (size_t)b * N_DIM + tid] = e / ssum;
        out[OUT_FB + (size_t)b * N_DIM + tid] = lg[N_DIM + tid];
    }
    if (tid == 0) {
        // jax.nn.softplus stable form: max(p,0) + log1p(exp(-|p|))
        float p = lg[360];
        float sp = fmaxf(p, 0.0f) + log1pf(expf(-fabsf(p)));
        out[OUT_PI + b] = fminf(sp, PI_MAX);
    }
}

// ---------------- launch ----------------
extern "C" void kernel_launch(void* const* d_in, const int* in_sizes, int n_in,
                              void* d_out, int out_size) {
    (void)in_sizes; (void)n_in; (void)out_size;
    const float* x_l4   = (const float*)d_in[0];
    const float* x_l23  = (const float*)d_in[1];
    const float* cue    = (const float*)d_in[2];
    const float* ts     = (const float*)d_in[3];
    const float* v_prev = (const float*)d_in[4];
    const float* z_prev = (const float*)d_in[5];
    const float* x_prev = (const float*)d_in[6];
    const float* b_prev = (const float*)d_in[7];
    const float* amask  = (const float*)d_in[8];
    const float* W_in   = (const float*)d_in[9];
    const float* b_in   = (const float*)d_in[10];
    const float* W_rec  = (const float*)d_in[11];
    const float* W_mu   = (const float*)d_in[12];
    const float* b_mu   = (const float*)d_in[13];
    const float* W_fb   = (const float*)d_in[14];
    const float* b_fb   = (const float*)d_in[15];
    const float* W_pi   = (const float*)d_in[16];
    const float* b_pi   = (const float*)d_in[17];
    float* out = (float*)d_out;

    pack_v2_kernel<<<(B_DIM * K1PAD + 255) / 256, 256>>>(x_l4, x_l23, cue, ts);
    pack_w2_kernel<<<(N2PAD * NV2 + 255) / 256, 256>>>(W_mu, b_mu, W_fb, b_fb, W_pi, b_pi);
    gemm1_kernel<<<dim3(32, 32), 256>>>(x_prev, W_in, W_rec, b_in,
                                        v_prev, z_prev, b_prev, amask, out);
    gemm2_kernel<<<dim3(3, 32), 256>>>(out);
    finish_kernel<<<B_DIM, 256>>>(out);
}

// round 5
// speedup vs baseline: 1.3126x; 1.3126x over previous
#include <cuda_runtime.h>
#include <cstdint>

// ---------------- problem dims ----------------
#define B_DIM   4096
#define N_DIM   180
#define NV2     4096
#define IN_DIM  542
#define K1PAD   544            // IN_DIM padded to mult of 16
#define N2PAD   384            // 180 mu + 180 fb + 1 pi, padded to mult of 128
#define KSPLIT  4              // gemm2 split-K factor

// output layout (flattened concat of reference tuple)
#define OUT_MU  0
#define OUT_PI  (B_DIM * N_DIM)
#define OUT_FB  (OUT_PI + B_DIM)
#define OUT_V   (OUT_FB + B_DIM * N_DIM)
#define OUT_Z   (OUT_V + (size_t)B_DIM * NV2)
#define OUT_X   (OUT_Z + (size_t)B_DIM * NV2)
#define OUT_B   (OUT_X + (size_t)B_DIM * NV2)

// constants (match python float64 -> f32 rounding)
#define BETA_MEM   0.951229424500714f
#define RHO_ADAPT  0.9950124791926823f
#define ONE_M_RHO  0.004987520807317688f
#define BETA_ADAPT 1.8f
#define ALPHA_F    0.9f
#define PI_MAX     10.0f

// ---------------- device scratch (no allocs allowed) ----------------
__device__ float g_v2[(size_t)B_DIM * K1PAD];                 // packed v2_input [B,544]
__device__ float g_w2[(size_t)N2PAD * NV2];                   // packed stage-2 W [384,4096]
__device__ float g_b2[N2PAD];                                 // packed stage-2 bias
__device__ float g_part[(size_t)KSPLIT * B_DIM * N2PAD];      // gemm2 split-K partials

// ---------------- pack kernels ----------------
__global__ void pack_v2_kernel(const float* __restrict__ xl4,
                               const float* __restrict__ xl23,
                               const float* __restrict__ cue,
                               const float* __restrict__ ts) {
    int i = blockIdx.x * blockDim.x + threadIdx.x;
    if (i >= B_DIM * K1PAD) return;
    int b = i / K1PAD, k = i % K1PAD;
    float v;
    if      (k < 180) v = xl4 [b * 180 + k];
    else if (k < 360) v = xl23[b * 180 + (k - 180)];
    else if (k < 540) v = cue [b * 180 + (k - 360)];
    else if (k < 542) v = ts  [b * 2   + (k - 540)];
    else              v = 0.0f;
    g_v2[i] = v;
}

__global__ void pack_w2_kernel(const float* __restrict__ Wmu, const float* __restrict__ bmu,
                               const float* __restrict__ Wfb, const float* __restrict__ bfb,
                               const float* __restrict__ Wpi, const float* __restrict__ bpi) {
    int i = blockIdx.x * blockDim.x + threadIdx.x;
    if (i < N2PAD) {
        float bv = 0.0f;
        if      (i < 180)  bv = bmu[i];
        else if (i < 360)  bv = bfb[i - 180];
        else if (i == 360) bv = bpi[0];
        g_b2[i] = bv;
    }
    if (i >= N2PAD * NV2) return;
    int r = i / NV2, k = i % NV2;
    float w = 0.0f;
    if      (r < 180)  w = Wmu[r * NV2 + k];
    else if (r < 360)  w = Wfb[(r - 180) * NV2 + k];
    else if (r == 360) w = Wpi[k];
    g_w2[i] = w;
}

// ---------------- GEMM micro-kernel: 128x128x16 tile, 8x8/thread -----------------
// Thread (tx,ty): rows ty*8..+7, cols {tx*4..+3} U {64+tx*4..+3}.
// acc[i][j]: j=0 -> cols tx*4+{0,1}, j=1 -> tx*4+{2,3}, j=2 -> 64+tx*4+{0,1}, j=3 -> 64+tx*4+{2,3}.
// Per element: single ascending-k fma.rn chain (IEEE-rn per lane) — FP order is
// identical to the R4 passing kernel; only the LDS width/mapping changed.
#define SROW 132   /* 528 B rows: 16B-aligned, enables LDS.128 */

__device__ __forceinline__ void mma_tile16(unsigned long long acc[8][4],
                                           const float (*As)[SROW],
                                           const float (*Bs)[SROW],
                                           int tx, int ty) {
#pragma unroll
    for (int k = 0; k < 16; k++) {
        float4 b0 = *(const float4*)(&Bs[k][tx * 4]);
        float4 b1 = *(const float4*)(&Bs[k][64 + tx * 4]);
        float4 a0 = *(const float4*)(&As[k][ty * 8]);
        float4 a1 = *(const float4*)(&As[k][ty * 8 + 4]);
        unsigned long long bp[4];
        asm("mov.b64 %0, {%1, %2};" : "=l"(bp[0]) : "f"(b0.x), "f"(b0.y));
        asm("mov.b64 %0, {%1, %2};" : "=l"(bp[1]) : "f"(b0.z), "f"(b0.w));
        asm("mov.b64 %0, {%1, %2};" : "=l"(bp[2]) : "f"(b1.x), "f"(b1.y));
        asm("mov.b64 %0, {%1, %2};" : "=l"(bp[3]) : "f"(b1.z), "f"(b1.w));
        float av[8] = {a0.x, a0.y, a0.z, a0.w, a1.x, a1.y, a1.z, a1.w};
#pragma unroll
        for (int i = 0; i < 8; i++) {
            unsigned long long a2;
            unsigned u = __float_as_uint(av[i]);
            asm("mov.b64 %0, {%1, %1};" : "=l"(a2) : "r"(u));
#pragma unroll
            for (int j = 0; j < 4; j++)
                asm("fma.rn.f32x2 %0, %1, %2, %0;"
                    : "+l"(acc[i][j]) : "l"(a2), "l"(bp[j]));
        }
    }
}

__device__ __forceinline__ void zero_acc(unsigned long long a[8][4]) {
#pragma unroll
    for (int i = 0; i < 8; i++)
#pragma unroll
        for (int j = 0; j < 4; j++) a[i][j] = 0ull;
}

__device__ __forceinline__ void fold_acc(unsigned long long acc[8][4],
                                         unsigned long long blk[8][4]) {
#pragma unroll
    for (int i = 0; i < 8; i++)
#pragma unroll
        for (int j = 0; j < 4; j++)
            asm("add.rn.f32x2 %0, %0, %1;" : "+l"(acc[i][j]) : "l"(blk[i][j]));
}

// store a prefetched 128x16 tile pair into shared (transposed), r/c derived from tid
__device__ __forceinline__ void store_tile(float (*As)[SROW], float (*Bs)[SROW],
                                           const float4 pa[2], const float4 pb[2],
                                           int tid) {
#pragma unroll
    for (int q = 0; q < 2; q++) {
        int l = tid + q * 256;
        int r = l >> 2, c = (l & 3) * 4;
        As[c + 0][r] = pa[q].x; As[c + 1][r] = pa[q].y;
        As[c + 2][r] = pa[q].z; As[c + 3][r] = pa[q].w;
        Bs[c + 0][r] = pb[q].x; Bs[c + 1][r] = pb[q].y;
        Bs[c + 2][r] = pb[q].z; Bs[c + 3][r] = pb[q].w;
    }
}

// ---------------- kernel 1: drive GEMM + fused elementwise state update ----------
// Two-level blocked accumulation (b=64) — bit-identical FP sequence to R4.
// drive = (Sum_A + b_in) + Sum_B; Sum_A stashed to out[OUT_V] between phases.
__global__ __launch_bounds__(256, 1)
void gemm1_kernel(const float* __restrict__ xprev,
                  const float* __restrict__ Win,
                  const float* __restrict__ Wrec,
                  const float* __restrict__ bin,
                  const float* __restrict__ vprev,
                  const float* __restrict__ zprev,
                  const float* __restrict__ bprev,
                  const float* __restrict__ amask,
                  float* __restrict__ out) {
    __shared__ __align__(16) float As[16][SROW];
    __shared__ __align__(16) float Bs[16][SROW];

    const int tid = threadIdx.x;
    const int tx = tid & 15, ty = tid >> 4;
    const int bm = blockIdx.y * 128;     // batch rows
    const int bn = blockIdx.x * 128;     // neuron cols
    const int lr = tid >> 2;             // loader row 0..63 (q adds 64)
    const int lc = (tid & 3) * 4;        // loader col group

    unsigned long long acc[8][4];        // master sum
    unsigned long long blk[8][4];        // fresh 64-k block sum
    zero_acc(acc);

    // ================= phase A: K over packed v2 (542 real / 544 pad) =================
    // A tile from g_v2 (stride K1PAD); B tile from Win (stride IN_DIM, guarded).
    {
        const int TA = K1PAD / 16;       // 34 tiles
        float4 pa[2]; float2 pbw[4];

        // prefetch helpers (phase A B-loader uses float2 lanes, 4 per thread)
        auto loadA = [&](int t, float4 pa_[2], float2 pb_[4]) {
            int kk = t * 16;
#pragma unroll
            for (int q = 0; q < 2; q++) {
                int r = lr + q * 64;
                pa_[q] = *(const float4*)(&g_v2[(size_t)(bm + r) * K1PAD + kk + lc]);
            }
#pragma unroll
            for (int q = 0; q < 4; q++) {
                int l = tid + q * 256;
                int r = l >> 3, c = (l & 7) * 2;
                int k = kk + c;
                float w0 = 0.0f, w1 = 0.0f;
                if (k + 1 < IN_DIM) {
                    float2 f = *(const float2*)(&Win[(size_t)(bn + r) * IN_DIM + k]);
                    w0 = f.x; w1 = f.y;
                } else if (k < IN_DIM) {
                    w0 = Win[(size_t)(bn + r) * IN_DIM + k];
                }
                pb_[q] = make_float2(w0, w1);
            }
        };

        loadA(0, pa, pbw);
        for (int t = 0; t < TA; t++) {
            if ((t & 3) == 0) zero_acc(blk);
            __syncthreads();
#pragma unroll
            for (int q = 0; q < 2; q++) {
                int r = lr + q * 64;
                As[lc + 0][r] = pa[q].x; As[lc + 1][r] = pa[q].y;
                As[lc + 2][r] = pa[q].z; As[lc + 3][r] = pa[q].w;
            }
#pragma unroll
            for (int q = 0; q < 4; q++) {
                int l = tid + q * 256;
                int r = l >> 3, c = (l & 7) * 2;
                Bs[c][r] = pbw[q].x; Bs[c + 1][r] = pbw[q].y;
            }
            __syncthreads();
            if (t + 1 < TA) loadA(t + 1, pa, pbw);
            mma_tile16(blk, As, Bs, tx, ty);
            if ((t & 3) == 3 || t == TA - 1) fold_acc(acc, blk);
        }
    }

    // ---- stash Sum_A (raw) into out[OUT_V]; reset master ----
#pragma unroll
    for (int i = 0; i < 8; i++) {
        int gr = bm + ty * 8 + i;
#pragma unroll
        for (int j = 0; j < 4; j++) {
            int gc = bn + ((j >> 1) * 64) + tx * 4 + (j & 1) * 2;
            *(unsigned long long*)(&out[OUT_V + (size_t)gr * NV2 + gc]) = acc[i][j];
        }
    }
    zero_acc(acc);

    // ================= phase B: K over x_prev (4096), W_rec =================
    {
        const int TB = NV2 / 16;         // 256 tiles
        float4 pa[2], pb[2];
        auto loadB = [&](int t, float4 pa_[2], float4 pb_[2]) {
            int kk = t * 16;
#pragma unroll
            for (int q = 0; q < 2; q++) {
                int r = lr + q * 64;
                pa_[q] = *(const float4*)(&xprev[(size_t)(bm + r) * NV2 + kk + lc]);
                pb_[q] = *(const float4*)(&Wrec [(size_t)(bn + r) * NV2 + kk + lc]);
            }
        };

        loadB(0, pa, pb);
        for (int t = 0; t < TB; t++) {
            if ((t & 3) == 0) zero_acc(blk);
            __syncthreads();
            store_tile(As, Bs, pa, pb, tid);
            __syncthreads();
            if (t + 1 < TB) loadB(t + 1, pa, pb);
            mma_tile16(blk, As, Bs, tx, ty);
            if ((t & 3) == 3) fold_acc(acc, blk);
        }
    }

    // ---- fused elementwise epilogue (explicit rn ops, reference order) ----
#pragma unroll
    for (int i = 0; i < 8; i++) {
        int gr = bm + ty * 8 + i;
#pragma unroll
        for (int j = 0; j < 4; j++) {
            int gc = bn + ((j >> 1) * 64) + tx * 4 + (j & 1) * 2;
            unsigned lo, hi;
            asm("mov.b64 {%0, %1}, %2;" : "=r"(lo), "=r"(hi) : "l"(acc[i][j]));
            size_t idx = (size_t)gr * NV2 + gc;
            float2 sA = *(const float2*)(&out[OUT_V + idx]);   // stashed Sum_A
            float2 bi = *(const float2*)(&bin[gc]);
            float2 am = *(const float2*)(&amask[gc]);
            float2 vp = *(const float2*)(&vprev[idx]);
            float2 zp = *(const float2*)(&zprev[idx]);
            float2 bp = *(const float2*)(&bprev[idx]);
            float2 xp = *(const float2*)(&xprev[idx]);

            float d0 = __fadd_rn(__fadd_rn(sA.x, bi.x), __uint_as_float(lo));
            float d1 = __fadd_rn(__fadd_rn(sA.y, bi.y), __uint_as_float(hi));

            float v0 = __fsub_rn(__fadd_rn(__fmul_rn(BETA_MEM, vp.x), d0), zp.x);
            float v1 = __fsub_rn(__fadd_rn(__fmul_rn(BETA_MEM, vp.y), d1), zp.y);
            float u0 = __fsub_rn(v0, __fadd_rn(1.0f, __fmul_rn(BETA_ADAPT, bp.x)));
            float u1 = __fsub_rn(v1, __fadd_rn(1.0f, __fmul_rn(BETA_ADAPT, bp.y)));
            float z0 = u0 > 0.0f ? 1.0f : 0.0f;
            float z1 = u1 > 0.0f ? 1.0f : 0.0f;
            float b0 = __fmul_rn(__fadd_rn(__fmul_rn(RHO_ADAPT, bp.x),
                                           __fmul_rn(ONE_M_RHO, z0)), am.x);
            float b1 = __fmul_rn(__fadd_rn(__fmul_rn(RHO_ADAPT, bp.y),
                                           __fmul_rn(ONE_M_RHO, z1)), am.y);
            float x0 = __fadd_rn(__fmul_rn(ALPHA_F, xp.x), z0);
            float x1 = __fadd_rn(__fmul_rn(ALPHA_F, xp.y), z1);

            *(float2*)(&out[OUT_V + idx]) = make_float2(v0, v1);
            *(float2*)(&out[OUT_Z + idx]) = make_float2(z0, z1);
            *(float2*)(&out[OUT_X + idx]) = make_float2(x0, x1);
            *(float2*)(&out[OUT_B + idx]) = make_float2(b0, b1);
        }
    }
}

// ---------------- kernel 2: stage-2 GEMM, split-K=4: partials = x @ W2.T ----------
__global__ __launch_bounds__(256, 2)
void gemm2_kernel(const float* __restrict__ out_base) {
    const float* x = out_base + OUT_X;
    __shared__ __align__(16) float As[16][SROW];
    __shared__ __align__(16) float Bs[16][SROW];

    const int tid = threadIdx.x;
    const int tx = tid & 15, ty = tid >> 4;
    const int bm = blockIdx.y * 128;
    const int bn = blockIdx.x * 128;     // 0..383
    const int ks = blockIdx.z;           // K split 0..3
    const int kbase = ks * (NV2 / KSPLIT);
    const int lr = tid >> 2;
    const int lc = (tid & 3) * 4;

    unsigned long long acc[8][4];
    zero_acc(acc);

    const int T = (NV2 / KSPLIT) / 16;   // 64 tiles
    float4 pa[2], pb[2];
    auto loadT = [&](int t, float4 pa_[2], float4 pb_[2]) {
        int kk = kbase + t * 16;
#pragma unroll
        for (int q = 0; q < 2; q++) {
            int r = lr + q * 64;
            pa_[q] = *(const float4*)(&x   [(size_t)(bm + r) * NV2 + kk + lc]);
            pb_[q] = *(const float4*)(&g_w2[(size_t)(bn + r) * NV2 + kk + lc]);
        }
    };

    loadT(0, pa, pb);
    for (int t = 0; t < T; t++) {
        __syncthreads();
        store_tile(As, Bs, pa, pb, tid);
        __syncthreads();
        if (t + 1 < T) loadT(t + 1, pa, pb);
        mma_tile16(acc, As, Bs, tx, ty);
    }

    float* part = &g_part[(size_t)ks * B_DIM * N2PAD];
#pragma unroll
    for (int i = 0; i < 8; i++) {
        int gr = bm + ty * 8 + i;
#pragma unroll
        for (int j = 0; j < 4; j++) {
            int gc = bn + ((j >> 1) * 64) + tx * 4 + (j & 1) * 2;
            *(unsigned long long*)(&part[(size_t)gr * N2PAD + gc]) = acc[i][j];
        }
    }
}

// ---------------- kernel 3: reduce partials + softmax / feedback / softplus -------
__device__ __forceinline__ float logit_at(int b, int c) {
    const size_t s = (size_t)B_DIM * N2PAD;
    size_t idx = (size_t)b * N2PAD + c;
    float v = __fadd_rn(g_part[idx], g_part[s + idx]);
    v = __fadd_rn(v, g_part[2 * s + idx]);
    v = __fadd_rn(v, g_part[3 * s + idx]);
    return __fadd_rn(v, g_b2[c]);
}

__global__ void finish_kernel(float* __restrict__ out) {
    int b = blockIdx.x;
    int tid = threadIdx.x;                    // 256 threads
    __shared__ float red[256];

    float l = (tid < N_DIM) ? logit_at(b, tid) : -3.0e38f;
    red[tid] = l;
    __syncthreads();
#pragma unroll
    for (int s = 128; s > 0; s >>= 1) {
        if (tid < s) red[tid] = fmaxf(red[tid], red[tid + s]);
        __syncthreads();
    }
    float m = red[0];
    __syncthreads();

    float e = (tid < N_DIM) ? expf(l - m) : 0.0f;
    red[tid] = e;
    __syncthreads();
#pragma unroll
    for (int s = 128; s > 0; s >>= 1) {
        if (tid < s) red[tid] += red[tid + s];
        __syncthreads();
    }
    float ssum = red[0];

    if (tid < N_DIM) {
        out[OUT_MU + (size_t)b * N_DIM + tid] = e / ssum;
        out[OUT_FB + (size_t)b * N_DIM + tid] = logit_at(b, N_DIM + tid);
    }
    if (tid == 0) {
        float p = logit_at(b, 360);
        float sp = fmaxf(p, 0.0f) + log1pf(expf(-fabsf(p)));
        out[OUT_PI + b] = fminf(sp, PI_MAX);
    }
}

// ---------------- launch ----------------
extern "C" void kernel_launch(void* const* d_in, const int* in_sizes, int n_in,
                              void* d_out, int out_size) {
    (void)in_sizes; (void)n_in; (void)out_size;
    const float* x_l4   = (const float*)d_in[0];
    const float* x_l23  = (const float*)d_in[1];
    const float* cue    = (const float*)d_in[2];
    const float* ts     = (const float*)d_in[3];
    const float* v_prev = (const float*)d_in[4];
    const float* z_prev = (const float*)d_in[5];
    const float* x_prev = (const float*)d_in[6];
    const float* b_prev = (const float*)d_in[7];
    const float* amask  = (const float*)d_in[8];
    const float* W_in   = (const float*)d_in[9];
    const float* b_in   = (const float*)d_in[10];
    const float* W_rec  = (const float*)d_in[11];
    const float* W_mu   = (const float*)d_in[12];
    const float* b_mu   = (const float*)d_in[13];
    const float* W_fb   = (const float*)d_in[14];
    const float* b_fb   = (const float*)d_in[15];
    const float* W_pi   = (const float*)d_in[16];
    const float* b_pi   = (const float*)d_in[17];
    float* out = (float*)d_out;

    pack_v2_kernel<<<(B_DIM * K1PAD + 255) / 256, 256>>>(x_l4, x_l23, cue, ts);
    pack_w2_kernel<<<(N2PAD * NV2 + 255) / 256, 256>>>(W_mu, b_mu, W_fb, b_fb, W_pi, b_pi);
    gemm1_kernel<<<dim3(32, 32), 256>>>(x_prev, W_in, W_rec, b_in,
                                        v_prev, z_prev, b_prev, amask, out);
    gemm2_kernel<<<dim3(3, 32, KSPLIT), 256>>>(out);
    finish_kernel<<<B_DIM, 256>>>(out);
}